// round 14
// baseline (speedup 1.0000x reference)
#include <cuda_runtime.h>

#define NMAX 100000
#define EMAX 300000

// ---------------- scratch (device globals; no allocation allowed) ----------------
__device__ float g_H [3L * NMAX * 128];   // in-proj outputs; layer-1 GAT outputs (ReLU'd) overwrite in place
__device__ float g_GL[9L * NMAX * 128];   // per-relation source projections
__device__ float g_GR[9L * NMAX * 128];   // per-relation dest   projections
__device__ int   g_cnt [9 * NMAX];
__device__ int   g_cur [9 * NMAX];
__device__ int   g_off [9 * (NMAX + 1)];
__device__ int   g_srcs[9 * EMAX];

// relation -> src/dst node-type (t=0, v=1, e=2)
__constant__ int c_srcT[9] = {0,0,1,0,2,1,2,1,2};
__constant__ int c_dstT[9] = {0,1,0,2,0,2,1,1,2};
// dst group (= dst type) -> its 3 incoming relations
__constant__ int c_grpRel[3][3] = {{0,2,4},{1,6,7},{3,5,8}};

// ---------------- f32x2 helpers (packed fp32 FMA, 2x FFMA rate on sm_103a) ------
__device__ __forceinline__ unsigned long long dup2(float a) {
    unsigned long long r;
    asm("mov.b64 %0, {%1, %1};" : "=l"(r) : "f"(a));
    return r;
}
__device__ __forceinline__ void fma2(unsigned long long &d, unsigned long long a,
                                     unsigned long long b) {
    asm("fma.rn.f32x2 %0, %1, %2, %0;" : "+l"(d) : "l"(a), "l"(b));
}
__device__ __forceinline__ void unpack2(unsigned long long v, float &lo, float &hi) {
    asm("mov.b64 {%0, %1}, %2;" : "=f"(lo), "=f"(hi) : "l"(v));
}

// ---------------- fallback (size mismatch): zero the output so failure is visible
__global__ __launch_bounds__(256) void zero_out_k(float* out, int n) {
    int i = blockIdx.x * blockDim.x + threadIdx.x;
    if (i < n) out[i] = 0.f;
}

// ---------------- CSR build ----------------
__global__ __launch_bounds__(256) void csr_zero(int M) {
    int i = blockIdx.x * blockDim.x + threadIdx.x;
    if (i < 9 * M) g_cnt[i] = 0;
}

__device__ __forceinline__ const int* pick_ei(int rel,
    const int* e0, const int* e1, const int* e2, const int* e3, const int* e4,
    const int* e5, const int* e6, const int* e7, const int* e8) {
    switch (rel) {
        case 0: return e0; case 1: return e1; case 2: return e2;
        case 3: return e3; case 4: return e4; case 5: return e5;
        case 6: return e6; case 7: return e7; default: return e8;
    }
}

// blockIdx.y = relation (no integer division in the hot path)
__global__ __launch_bounds__(256)
void csr_hist(const int* e0, const int* e1, const int* e2, const int* e3,
              const int* e4, const int* e5, const int* e6, const int* e7,
              const int* e8, int M, int E) {
    int e = blockIdx.x * blockDim.x + threadIdx.x;
    if (e >= E) return;
    int rel = blockIdx.y;
    const int* ei = pick_ei(rel, e0,e1,e2,e3,e4,e5,e6,e7,e8);
    atomicAdd(&g_cnt[rel * M + ei[E + e]], 1);
}

// one block per relation, 1024 threads, warp-scan + cross-warp scan (2 syncs/chunk)
__global__ __launch_bounds__(1024) void csr_scan(int M) {
    int rel = blockIdx.x;
    __shared__ int wsum[32];
    int tid = threadIdx.x;
    int lane = tid & 31, wid = tid >> 5;
    int carry = 0;
    for (int base = 0; base < M; base += 1024) {
        int i = base + tid;
        int v = (i < M) ? g_cnt[rel * M + i] : 0;
        // inclusive warp scan
        int x = v;
        #pragma unroll
        for (int off = 1; off < 32; off <<= 1) {
            int y = __shfl_up_sync(0xffffffffu, x, off);
            if (lane >= off) x += y;
        }
        if (lane == 31) wsum[wid] = x;
        __syncthreads();
        if (wid == 0) {
            int s = wsum[lane];
            #pragma unroll
            for (int off = 1; off < 32; off <<= 1) {
                int y = __shfl_up_sync(0xffffffffu, s, off);
                if (lane >= off) s += y;
            }
            wsum[lane] = s;
        }
        __syncthreads();
        int winc = (wid > 0) ? wsum[wid - 1] : 0;     // exclusive warp prefix
        int incl = x + winc;                           // inclusive over block chunk
        if (i < M) {
            int ex = carry + incl - v;                 // exclusive global
            g_off[rel * (M + 1) + i] = ex;
            g_cur[rel * M + i]       = ex;
        }
        carry += wsum[31];
        __syncthreads();
    }
    if (tid == 0) g_off[rel * (M + 1) + M] = carry;
}

// blockIdx.y = relation
__global__ __launch_bounds__(256)
void csr_scatter(const int* e0, const int* e1, const int* e2, const int* e3,
                 const int* e4, const int* e5, const int* e6, const int* e7,
                 const int* e8, int M, int E) {
    int e = blockIdx.x * blockDim.x + threadIdx.x;
    if (e >= E) return;
    int rel = blockIdx.y;
    const int* ei = pick_ei(rel, e0,e1,e2,e3,e4,e5,e6,e7,e8);
    int s = ei[e], d = ei[E + e];
    int pos = atomicAdd(&g_cur[rel * M + d], 1);
    g_srcs[rel * E + pos] = s;
}

// ---------------- in-projection: H = X(100k x 16) @ W(16x128) + b ----------------
__global__ __launch_bounds__(256)
void in_proj_k(const float* __restrict__ X0, const float* __restrict__ X1,
               const float* __restrict__ X2,
               const float* __restrict__ Wt, const float* __restrict__ bt,
               const float* __restrict__ Wv, const float* __restrict__ bv,
               const float* __restrict__ We, const float* __restrict__ be,
               int M) {
    int type = blockIdx.z;
    const float* X  = type == 0 ? X0 : (type == 1 ? X1 : X2);
    const float* W  = type == 0 ? Wt : (type == 1 ? Wv : We);
    const float* bb = type == 0 ? bt : (type == 1 ? bv : be);
    float* H = g_H + (size_t)type * M * 128;

    __shared__ __align__(16) float Ws[2048];
    __shared__ __align__(16) float bs[128];
    int tid = threadIdx.x;
    for (int i = tid; i < 2048; i += 256) Ws[i] = W[i];
    if (tid < 128) bs[tid] = bb[tid];
    __syncthreads();

    int g = blockIdx.x * 256 + tid;
    int row = g >> 5, c4 = g & 31;
    if (row >= M) return;

    float x[16];
    const float4* xr = (const float4*)(X + (size_t)row * 16);
    *(float4*)&x[0]  = xr[0];
    *(float4*)&x[4]  = xr[1];
    *(float4*)&x[8]  = xr[2];
    *(float4*)&x[12] = xr[3];

    const float4* Wf = (const float4*)Ws;
    float4 acc = ((const float4*)bs)[c4];
    #pragma unroll
    for (int k = 0; k < 16; k++) {
        float4 w = Wf[k * 32 + c4];
        acc.x = fmaf(x[k], w.x, acc.x);
        acc.y = fmaf(x[k], w.y, acc.y);
        acc.z = fmaf(x[k], w.z, acc.z);
        acc.w = fmaf(x[k], w.w, acc.w);
    }
    ((float4*)H)[(size_t)row * 32 + c4] = acc;
}

// ---------------- batched SGEMM: C[rel,side] = A(M x 128) @ W(128 x 128) --------
// blockIdx.z = relation, blockIdx.y = side (0 = Wl->GL, 1 = Wr->GR).
// A is always g_H (layer-1 inputs, or ReLU'd layer-1 outputs written in place).
// 128x128 tile per block, BK=16, 256 threads, 8x8 microtile, packed f32x2 FMAs.
__global__ __launch_bounds__(256, 2)
void gemm_k(const float* __restrict__ Wl9, const float* __restrict__ Wr9, int M) {
    int rel = blockIdx.z;
    int isR = blockIdx.y;
    int t = isR ? c_dstT[rel] : c_srcT[rel];
    const float* __restrict__ A = g_H + (size_t)t * M * 128;
    const float* __restrict__ B = (isR ? Wr9 : Wl9) + rel * 16384;
    float* __restrict__ C = (isR ? g_GR : g_GL) + (size_t)rel * M * 128;

    __shared__ __align__(16) float As[16][128];
    __shared__ __align__(16) float Bs[16][128];

    int tid = threadIdx.x;
    int tx = tid & 15;      // 8 cols each
    int ty = tid >> 4;      // 8 rows each
    int row0 = blockIdx.x * 128;

    unsigned long long acc[8][4];
    #pragma unroll
    for (int i = 0; i < 8; i++)
        #pragma unroll
        for (int j = 0; j < 4; j++) acc[i][j] = 0ULL;

    for (int k0 = 0; k0 < 128; k0 += 16) {
        #pragma unroll
        for (int i = 0; i < 2; i++) {           // A: 128 rows x 16 k, transposed store
            int idx = tid * 2 + i;
            int r = idx >> 2, c4 = idx & 3;
            int grow = row0 + r;
            float4 v = make_float4(0.f, 0.f, 0.f, 0.f);
            if (grow < M) v = ((const float4*)A)[(size_t)grow * 32 + (k0 >> 2) + c4];
            As[c4 * 4 + 0][r] = v.x;
            As[c4 * 4 + 1][r] = v.y;
            As[c4 * 4 + 2][r] = v.z;
            As[c4 * 4 + 3][r] = v.w;
        }
        #pragma unroll
        for (int i = 0; i < 2; i++) {           // B: 16 k x 128 n
            int idx = tid * 2 + i;
            int r = idx >> 5, c4 = idx & 31;
            ((float4*)&Bs[r][0])[c4] = ((const float4*)B)[(k0 + r) * 32 + c4];
        }
        __syncthreads();

        #pragma unroll
        for (int kk = 0; kk < 16; kk++) {
            float a[8];
            *(float4*)&a[0] = *(const float4*)&As[kk][ty * 8];
            *(float4*)&a[4] = *(const float4*)&As[kk][ty * 8 + 4];
            unsigned long long bb[4];
            #pragma unroll
            for (int j = 0; j < 4; j++)
                bb[j] = *(const unsigned long long*)&Bs[kk][tx * 8 + 2 * j];
            #pragma unroll
            for (int i = 0; i < 8; i++) {
                unsigned long long aa = dup2(a[i]);
                #pragma unroll
                for (int j = 0; j < 4; j++) fma2(acc[i][j], aa, bb[j]);
            }
        }
        __syncthreads();
    }

    #pragma unroll
    for (int i = 0; i < 8; i++) {
        int grow = row0 + ty * 8 + i;
        if (grow < M) {
            float4 o0, o1;
            unpack2(acc[i][0], o0.x, o0.y);
            unpack2(acc[i][1], o0.z, o0.w);
            unpack2(acc[i][2], o1.x, o1.y);
            unpack2(acc[i][3], o1.z, o1.w);
            float4* Cp = (float4*)C + (size_t)grow * 32 + tx * 2;
            Cp[0] = o0;
            Cp[1] = o1;
        }
    }
}

// ---------------- fused GATv2: warp per dst node, 3 relations, online softmax ---
// blockIdx.y = dst group (0=t, 1=v, 2=e); relations from c_grpRel.
// Layer 1 (useDout=0): writes relu(result) back into g_H (in place).
// Layer 2 (useDout=1): writes raw result to d_out.
// Edge loop 2-way software-pipelined: both gathers issue before the sequential
// online-softmax update, doubling per-warp MLP on the L2/DRAM gathers.
__global__ __launch_bounds__(256)
void gat_fused(const float* __restrict__ att9, const float* __restrict__ bc9,
               int useDout, float* __restrict__ dout, int M, int E) {
    int grp = blockIdx.y;
    int w = (blockIdx.x * blockDim.x + threadIdx.x) >> 5;
    int lane = threadIdx.x & 31;   // lanes 0-15: head 0 (c 0..63), 16-31: head 1
    if (w >= M) return;
    float* OUT = (useDout ? dout : g_H) + (size_t)grp * M * 128;
    const float NEGINF = __int_as_float(0xff800000u);

    float4 accT = make_float4(0.f, 0.f, 0.f, 0.f);
    float4 bsum = make_float4(0.f, 0.f, 0.f, 0.f);

    #pragma unroll
    for (int j = 0; j < 3; j++) {
        int r = c_grpRel[grp][j];
        const float4* GL = (const float4*)g_GL + (size_t)r * M * 32;
        const float4* GR = (const float4*)g_GR + (size_t)r * M * 32;
        float4 gr = GR[(size_t)w * 32 + lane];
        float4 aw = ((const float4*)att9)[r * 32 + lane];
        float4 b4 = ((const float4*)bc9)[r * 32 + lane];
        bsum.x += b4.x; bsum.y += b4.y; bsum.z += b4.z; bsum.w += b4.w;

        int beg = g_off[r * (M + 1) + w];
        int end = g_off[r * (M + 1) + w + 1];
        const int* sp = g_srcs + (size_t)r * E;

        float mh = NEGINF, den = 0.f;
        float4 acc = make_float4(0.f, 0.f, 0.f, 0.f);

        int i = beg;
        // ---- 2-edge pipelined main loop ----
        for (; i + 2 <= end; i += 2) {
            int s0 = sp[i], s1 = sp[i + 1];
            float4 g0 = GL[(size_t)s0 * 32 + lane];   // both gathers in flight
            float4 g1 = GL[(size_t)s1 * 32 + lane];

            float sx = g0.x + gr.x, sy = g0.y + gr.y, sz = g0.z + gr.z, sw = g0.w + gr.w;
            float t0 = (sx > 0.f ? sx : 0.2f * sx) * aw.x
                     + (sy > 0.f ? sy : 0.2f * sy) * aw.y
                     + (sz > 0.f ? sz : 0.2f * sz) * aw.z
                     + (sw > 0.f ? sw : 0.2f * sw) * aw.w;
            float ux = g1.x + gr.x, uy = g1.y + gr.y, uz = g1.z + gr.z, uw = g1.w + gr.w;
            float t1 = (ux > 0.f ? ux : 0.2f * ux) * aw.x
                     + (uy > 0.f ? uy : 0.2f * uy) * aw.y
                     + (uz > 0.f ? uz : 0.2f * uz) * aw.z
                     + (uw > 0.f ? uw : 0.2f * uw) * aw.w;

            t0 += __shfl_xor_sync(0xffffffffu, t0, 8);
            t1 += __shfl_xor_sync(0xffffffffu, t1, 8);
            t0 += __shfl_xor_sync(0xffffffffu, t0, 4);
            t1 += __shfl_xor_sync(0xffffffffu, t1, 4);
            t0 += __shfl_xor_sync(0xffffffffu, t0, 2);
            t1 += __shfl_xor_sync(0xffffffffu, t1, 2);
            t0 += __shfl_xor_sync(0xffffffffu, t0, 1);
            t1 += __shfl_xor_sync(0xffffffffu, t1, 1);   // per-16-lane (head) sums

            // joint online-softmax update for both edges (exact)
            float mn = fmaxf(mh, fmaxf(t0, t1));
            float sc = __expf(mh - mn);     // 0 when mh == -inf
            float p0 = __expf(t0 - mn);
            float p1 = __expf(t1 - mn);
            den = den * sc + p0 + p1;
            acc.x = acc.x * sc + p0 * g0.x + p1 * g1.x;
            acc.y = acc.y * sc + p0 * g0.y + p1 * g1.y;
            acc.z = acc.z * sc + p0 * g0.z + p1 * g1.z;
            acc.w = acc.w * sc + p0 * g0.w + p1 * g1.w;
            mh = mn;
        }
        // ---- remainder edge ----
        for (; i < end; i++) {
            int s = sp[i];
            float4 g = GL[(size_t)s * 32 + lane];
            float sx = g.x + gr.x, sy = g.y + gr.y, sz = g.z + gr.z, sw = g.w + gr.w;
            float v = (sx > 0.f ? sx : 0.2f * sx) * aw.x
                    + (sy > 0.f ? sy : 0.2f * sy) * aw.y
                    + (sz > 0.f ? sz : 0.2f * sz) * aw.z
                    + (sw > 0.f ? sw : 0.2f * sw) * aw.w;
            v += __shfl_xor_sync(0xffffffffu, v, 8);
            v += __shfl_xor_sync(0xffffffffu, v, 4);
            v += __shfl_xor_sync(0xffffffffu, v, 2);
            v += __shfl_xor_sync(0xffffffffu, v, 1);

            float mn = fmaxf(mh, v);
            float sc = __expf(mh - mn);
            float p  = __expf(v - mn);
            den = den * sc + p;
            acc.x = acc.x * sc + p * g.x;
            acc.y = acc.y * sc + p * g.y;
            acc.z = acc.z * sc + p * g.z;
            acc.w = acc.w * sc + p * g.w;
            mh = mn;
        }
        float inv = 1.f / (den + 1e-16f);
        accT.x += acc.x * inv;
        accT.y += acc.y * inv;
        accT.z += acc.z * inv;
        accT.w += acc.w * inv;
    }
    float4 o;
    o.x = accT.x + bsum.x;
    o.y = accT.y + bsum.y;
    o.z = accT.z + bsum.z;
    o.w = accT.w + bsum.w;
    if (!useDout) {          // inter-layer ReLU folded into the store
        o.x = fmaxf(o.x, 0.f); o.y = fmaxf(o.y, 0.f);
        o.z = fmaxf(o.z, 0.f); o.w = fmaxf(o.w, 0.f);
    }
    ((float4*)OUT)[(size_t)w * 32 + lane] = o;
}

// ---------------- driver ----------------
extern "C" void kernel_launch(void* const* d_in, const int* in_sizes, int n_in,
                              void* d_out, int out_size) {
    const float* xt = (const float*)d_in[0];
    const float* xv = (const float*)d_in[1];
    const float* xe = (const float*)d_in[2];
    const int* e0 = (const int*)d_in[3];
    const int* e1 = (const int*)d_in[4];
    const int* e2 = (const int*)d_in[5];
    const int* e3 = (const int*)d_in[6];
    const int* e4 = (const int*)d_in[7];
    const int* e5 = (const int*)d_in[8];
    const int* e6 = (const int*)d_in[9];
    const int* e7 = (const int*)d_in[10];
    const int* e8 = (const int*)d_in[11];
    const float* Wt = (const float*)d_in[12];
    const float* bt = (const float*)d_in[13];
    const float* Wv = (const float*)d_in[14];
    const float* bv = (const float*)d_in[15];
    const float* We = (const float*)d_in[16];
    const float* be = (const float*)d_in[17];
    const float* Wl1 = (const float*)d_in[18];
    const float* Wr1 = (const float*)d_in[19];
    const float* att1 = (const float*)d_in[20];
    const float* bc1 = (const float*)d_in[21];
    const float* Wl2 = (const float*)d_in[22];
    const float* Wr2 = (const float*)d_in[23];
    const float* att2 = (const float*)d_in[24];
    const float* bc2 = (const float*)d_in[25];

    int M = in_sizes[0] / 16;   // nodes per type
    int E = in_sizes[3] / 2;    // edges per relation
    float* out = (float*)d_out;
    if (M <= 0 || M > NMAX || E <= 0 || E > EMAX) {
        // visible failure mode (rel_err report) instead of empty capture
        zero_out_k<<<(out_size + 255) / 256, 256>>>(out, out_size);
        return;
    }

    // CSR build (per relation, reused by both layers)
    csr_zero<<<(9 * M + 255) / 256, 256>>>(M);
    csr_hist<<<dim3((E + 255) / 256, 9), 256>>>(e0,e1,e2,e3,e4,e5,e6,e7,e8, M, E);
    csr_scan<<<9, 1024>>>(M);
    csr_scatter<<<dim3((E + 255) / 256, 9), 256>>>(e0,e1,e2,e3,e4,e5,e6,e7,e8, M, E);

    // in-projection
    in_proj_k<<<dim3((M * 32 + 255) / 256, 1, 3), 256>>>(xt, xv, xe,
                                                         Wt, bt, Wv, bv, We, be, M);

    dim3 gg((M + 127) / 128, 2, 9);            // y: Wl/Wr side, z: relation
    dim3 fg((M * 32 + 255) / 256, 3);          // y: dst group

    // ---- layer 1 (reads g_H, writes relu(out) back into g_H) ----
    gemm_k<<<gg, 256>>>(Wl1, Wr1, M);
    gat_fused<<<fg, 256>>>(att1, bc1, 0, out, M, E);

    // ---- layer 2 (reads g_H, writes d_out) ----
    gemm_k<<<gg, 256>>>(Wl2, Wr2, M);
    gat_fused<<<fg, 256>>>(att2, bc2, 1, out, M, E);
}

// round 16
// speedup vs baseline: 1.1084x; 1.1084x over previous
#include <cuda_runtime.h>

#define NMAX 100000
#define EMAX 300000

// ---------------- scratch (device globals; no allocation allowed) ----------------
__device__ float g_H [3L * NMAX * 128];   // in-proj outputs; layer-1 GAT outputs (ReLU'd) overwrite in place
__device__ float g_GL[9L * NMAX * 128];   // per-relation source projections
__device__ float g_GR[9L * NMAX * 128];   // per-relation dest   projections
__device__ int   g_cnt [9 * NMAX];
__device__ int   g_cur [9 * NMAX];
__device__ int   g_off [9 * (NMAX + 1)];
__device__ int   g_srcs[9 * EMAX];

// relation -> src/dst node-type (t=0, v=1, e=2)
__constant__ int c_srcT[9] = {0,0,1,0,2,1,2,1,2};
__constant__ int c_dstT[9] = {0,1,0,2,0,2,1,1,2};
// dst group (= dst type) -> its 3 incoming relations
__constant__ int c_grpRel[3][3] = {{0,2,4},{1,6,7},{3,5,8}};

// ---------------- f32x2 helpers (packed fp32 FMA, 2x FFMA rate on sm_103a) ------
__device__ __forceinline__ unsigned long long dup2(float a) {
    unsigned long long r;
    asm("mov.b64 %0, {%1, %1};" : "=l"(r) : "f"(a));
    return r;
}
__device__ __forceinline__ void fma2(unsigned long long &d, unsigned long long a,
                                     unsigned long long b) {
    asm("fma.rn.f32x2 %0, %1, %2, %0;" : "+l"(d) : "l"(a), "l"(b));
}
__device__ __forceinline__ void unpack2(unsigned long long v, float &lo, float &hi) {
    asm("mov.b64 {%0, %1}, %2;" : "=f"(lo), "=f"(hi) : "l"(v));
}

// ---------------- fallback (size mismatch): zero the output so failure is visible
__global__ __launch_bounds__(256) void zero_out_k(float* out, int n) {
    int i = blockIdx.x * blockDim.x + threadIdx.x;
    if (i < n) out[i] = 0.f;
}

// ---------------- CSR build ----------------
__global__ __launch_bounds__(256) void csr_zero(int M) {
    int i = blockIdx.x * blockDim.x + threadIdx.x;
    if (i < 9 * M) g_cnt[i] = 0;
}

__device__ __forceinline__ const int* pick_ei(int rel,
    const int* e0, const int* e1, const int* e2, const int* e3, const int* e4,
    const int* e5, const int* e6, const int* e7, const int* e8) {
    switch (rel) {
        case 0: return e0; case 1: return e1; case 2: return e2;
        case 3: return e3; case 4: return e4; case 5: return e5;
        case 6: return e6; case 7: return e7; default: return e8;
    }
}

// blockIdx.y = relation (no integer division in the hot path)
__global__ __launch_bounds__(256)
void csr_hist(const int* e0, const int* e1, const int* e2, const int* e3,
              const int* e4, const int* e5, const int* e6, const int* e7,
              const int* e8, int M, int E) {
    int e = blockIdx.x * blockDim.x + threadIdx.x;
    if (e >= E) return;
    int rel = blockIdx.y;
    const int* ei = pick_ei(rel, e0,e1,e2,e3,e4,e5,e6,e7,e8);
    atomicAdd(&g_cnt[rel * M + ei[E + e]], 1);
}

// one block per relation, 1024 threads, warp-scan + cross-warp scan (2 syncs/chunk)
__global__ __launch_bounds__(1024) void csr_scan(int M) {
    int rel = blockIdx.x;
    __shared__ int wsum[32];
    int tid = threadIdx.x;
    int lane = tid & 31, wid = tid >> 5;
    int carry = 0;
    for (int base = 0; base < M; base += 1024) {
        int i = base + tid;
        int v = (i < M) ? g_cnt[rel * M + i] : 0;
        // inclusive warp scan
        int x = v;
        #pragma unroll
        for (int off = 1; off < 32; off <<= 1) {
            int y = __shfl_up_sync(0xffffffffu, x, off);
            if (lane >= off) x += y;
        }
        if (lane == 31) wsum[wid] = x;
        __syncthreads();
        if (wid == 0) {
            int s = wsum[lane];
            #pragma unroll
            for (int off = 1; off < 32; off <<= 1) {
                int y = __shfl_up_sync(0xffffffffu, s, off);
                if (lane >= off) s += y;
            }
            wsum[lane] = s;
        }
        __syncthreads();
        int winc = (wid > 0) ? wsum[wid - 1] : 0;     // exclusive warp prefix
        int incl = x + winc;                           // inclusive over block chunk
        if (i < M) {
            int ex = carry + incl - v;                 // exclusive global
            g_off[rel * (M + 1) + i] = ex;
            g_cur[rel * M + i]       = ex;
        }
        carry += wsum[31];
        __syncthreads();
    }
    if (tid == 0) g_off[rel * (M + 1) + M] = carry;
}

// blockIdx.y = relation
__global__ __launch_bounds__(256)
void csr_scatter(const int* e0, const int* e1, const int* e2, const int* e3,
                 const int* e4, const int* e5, const int* e6, const int* e7,
                 const int* e8, int M, int E) {
    int e = blockIdx.x * blockDim.x + threadIdx.x;
    if (e >= E) return;
    int rel = blockIdx.y;
    const int* ei = pick_ei(rel, e0,e1,e2,e3,e4,e5,e6,e7,e8);
    int s = ei[e], d = ei[E + e];
    int pos = atomicAdd(&g_cur[rel * M + d], 1);
    g_srcs[rel * E + pos] = s;
}

// ---------------- in-projection: H = X(100k x 16) @ W(16x128) + b ----------------
__global__ __launch_bounds__(256)
void in_proj_k(const float* __restrict__ X0, const float* __restrict__ X1,
               const float* __restrict__ X2,
               const float* __restrict__ Wt, const float* __restrict__ bt,
               const float* __restrict__ Wv, const float* __restrict__ bv,
               const float* __restrict__ We, const float* __restrict__ be,
               int M) {
    int type = blockIdx.z;
    const float* X  = type == 0 ? X0 : (type == 1 ? X1 : X2);
    const float* W  = type == 0 ? Wt : (type == 1 ? Wv : We);
    const float* bb = type == 0 ? bt : (type == 1 ? bv : be);
    float* H = g_H + (size_t)type * M * 128;

    __shared__ __align__(16) float Ws[2048];
    __shared__ __align__(16) float bs[128];
    int tid = threadIdx.x;
    for (int i = tid; i < 2048; i += 256) Ws[i] = W[i];
    if (tid < 128) bs[tid] = bb[tid];
    __syncthreads();

    int g = blockIdx.x * 256 + tid;
    int row = g >> 5, c4 = g & 31;
    if (row >= M) return;

    float x[16];
    const float4* xr = (const float4*)(X + (size_t)row * 16);
    *(float4*)&x[0]  = xr[0];
    *(float4*)&x[4]  = xr[1];
    *(float4*)&x[8]  = xr[2];
    *(float4*)&x[12] = xr[3];

    const float4* Wf = (const float4*)Ws;
    float4 acc = ((const float4*)bs)[c4];
    #pragma unroll
    for (int k = 0; k < 16; k++) {
        float4 w = Wf[k * 32 + c4];
        acc.x = fmaf(x[k], w.x, acc.x);
        acc.y = fmaf(x[k], w.y, acc.y);
        acc.z = fmaf(x[k], w.z, acc.z);
        acc.w = fmaf(x[k], w.w, acc.w);
    }
    ((float4*)H)[(size_t)row * 32 + c4] = acc;
}

// ---------------- batched SGEMM: C[rel,side] = A(M x 128) @ W(128 x 128) --------
// blockIdx.z = relation, blockIdx.y = side (0 = Wl->GL, 1 = Wr->GR).
// 128x128 tile per block, BK=16, 256 threads, 8x8 microtile, packed f32x2 FMAs.
// Bs uses an interleaved-pair layout: element n of row kk lives at
//   j*32 + tx*2 + e   (n = tx*8 + 2j + e, tx=n>>3, j=(n>>1)&3, e=n&1)
// so the inner-loop 8B reads are CONSECUTIVE across tx -> conflict-free LDS.
__global__ __launch_bounds__(256, 2)
void gemm_k(const float* __restrict__ Wl9, const float* __restrict__ Wr9, int M) {
    int rel = blockIdx.z;
    int isR = blockIdx.y;
    int t = isR ? c_dstT[rel] : c_srcT[rel];
    const float* __restrict__ A = g_H + (size_t)t * M * 128;
    const float* __restrict__ B = (isR ? Wr9 : Wl9) + rel * 16384;
    float* __restrict__ C = (isR ? g_GR : g_GL) + (size_t)rel * M * 128;

    __shared__ __align__(16) float As[16][128];
    __shared__ __align__(16) float Bs[16][128];   // interleaved-pair layout

    int tid = threadIdx.x;
    int tx = tid & 15;      // 8 cols each
    int ty = tid >> 4;      // 8 rows each
    int row0 = blockIdx.x * 128;

    unsigned long long acc[8][4];
    #pragma unroll
    for (int i = 0; i < 8; i++)
        #pragma unroll
        for (int j = 0; j < 4; j++) acc[i][j] = 0ULL;

    for (int k0 = 0; k0 < 128; k0 += 16) {
        #pragma unroll
        for (int i = 0; i < 2; i++) {           // A: 128 rows x 16 k, transposed store
            int idx = tid * 2 + i;
            int r = idx >> 2, c4 = idx & 3;
            int grow = row0 + r;
            float4 v = make_float4(0.f, 0.f, 0.f, 0.f);
            if (grow < M) v = ((const float4*)A)[(size_t)grow * 32 + (k0 >> 2) + c4];
            As[c4 * 4 + 0][r] = v.x;
            As[c4 * 4 + 1][r] = v.y;
            As[c4 * 4 + 2][r] = v.z;
            As[c4 * 4 + 3][r] = v.w;
        }
        #pragma unroll
        for (int i = 0; i < 2; i++) {           // B: 16 k x 128 n, interleaved store
            int idx = tid * 2 + i;
            int r = idx >> 5, c4 = idx & 31;
            float4 v = ((const float4*)B)[(k0 + r) * 32 + c4];
            // n0 = c4*4; tx0 = c4>>1; jbase = (c4&1)*2
            int base = ((c4 & 1) * 2) * 32 + (c4 >> 1) * 2;
            *(float2*)&Bs[r][base]      = make_float2(v.x, v.y);   // j = jbase
            *(float2*)&Bs[r][base + 32] = make_float2(v.z, v.w);   // j = jbase+1
        }
        __syncthreads();

        #pragma unroll
        for (int kk = 0; kk < 16; kk++) {
            float a[8];
            *(float4*)&a[0] = *(const float4*)&As[kk][ty * 8];
            *(float4*)&a[4] = *(const float4*)&As[kk][ty * 8 + 4];
            unsigned long long bb[4];
            #pragma unroll
            for (int j = 0; j < 4; j++)     // consecutive 8B across tx: conflict-free
                bb[j] = *(const unsigned long long*)&Bs[kk][j * 32 + tx * 2];
            #pragma unroll
            for (int i = 0; i < 8; i++) {
                unsigned long long aa = dup2(a[i]);
                #pragma unroll
                for (int j = 0; j < 4; j++) fma2(acc[i][j], aa, bb[j]);
            }
        }
        __syncthreads();
    }

    #pragma unroll
    for (int i = 0; i < 8; i++) {
        int grow = row0 + ty * 8 + i;
        if (grow < M) {
            float4 o0, o1;
            unpack2(acc[i][0], o0.x, o0.y);
            unpack2(acc[i][1], o0.z, o0.w);
            unpack2(acc[i][2], o1.x, o1.y);
            unpack2(acc[i][3], o1.z, o1.w);
            float4* Cp = (float4*)C + (size_t)grow * 32 + tx * 2;
            Cp[0] = o0;
            Cp[1] = o1;
        }
    }
}

// ---------------- fused GATv2: warp per dst node, 3 relations, online softmax ---
// blockIdx.y = dst group (0=t, 1=v, 2=e); relations from c_grpRel.
// Layer 1 (useDout=0): writes relu(result) back into g_H (in place).
// Layer 2 (useDout=1): writes raw result to d_out.
// Edge loop 2-way software-pipelined: both gathers issue before the sequential
// online-softmax update, doubling per-warp MLP on the L2/DRAM gathers.
__global__ __launch_bounds__(256)
void gat_fused(const float* __restrict__ att9, const float* __restrict__ bc9,
               int useDout, float* __restrict__ dout, int M, int E) {
    int grp = blockIdx.y;
    int w = (blockIdx.x * blockDim.x + threadIdx.x) >> 5;
    int lane = threadIdx.x & 31;   // lanes 0-15: head 0 (c 0..63), 16-31: head 1
    if (w >= M) return;
    float* OUT = (useDout ? dout : g_H) + (size_t)grp * M * 128;
    const float NEGINF = __int_as_float(0xff800000u);

    float4 accT = make_float4(0.f, 0.f, 0.f, 0.f);
    float4 bsum = make_float4(0.f, 0.f, 0.f, 0.f);

    #pragma unroll
    for (int j = 0; j < 3; j++) {
        int r = c_grpRel[grp][j];
        const float4* GL = (const float4*)g_GL + (size_t)r * M * 32;
        const float4* GR = (const float4*)g_GR + (size_t)r * M * 32;
        float4 gr = GR[(size_t)w * 32 + lane];
        float4 aw = ((const float4*)att9)[r * 32 + lane];
        float4 b4 = ((const float4*)bc9)[r * 32 + lane];
        bsum.x += b4.x; bsum.y += b4.y; bsum.z += b4.z; bsum.w += b4.w;

        int beg = g_off[r * (M + 1) + w];
        int end = g_off[r * (M + 1) + w + 1];
        const int* sp = g_srcs + (size_t)r * E;

        float mh = NEGINF, den = 0.f;
        float4 acc = make_float4(0.f, 0.f, 0.f, 0.f);

        int i = beg;
        // ---- 2-edge pipelined main loop ----
        for (; i + 2 <= end; i += 2) {
            int s0 = sp[i], s1 = sp[i + 1];
            float4 g0 = GL[(size_t)s0 * 32 + lane];   // both gathers in flight
            float4 g1 = GL[(size_t)s1 * 32 + lane];

            float sx = g0.x + gr.x, sy = g0.y + gr.y, sz = g0.z + gr.z, sw = g0.w + gr.w;
            float t0 = (sx > 0.f ? sx : 0.2f * sx) * aw.x
                     + (sy > 0.f ? sy : 0.2f * sy) * aw.y
                     + (sz > 0.f ? sz : 0.2f * sz) * aw.z
                     + (sw > 0.f ? sw : 0.2f * sw) * aw.w;
            float ux = g1.x + gr.x, uy = g1.y + gr.y, uz = g1.z + gr.z, uw = g1.w + gr.w;
            float t1 = (ux > 0.f ? ux : 0.2f * ux) * aw.x
                     + (uy > 0.f ? uy : 0.2f * uy) * aw.y
                     + (uz > 0.f ? uz : 0.2f * uz) * aw.z
                     + (uw > 0.f ? uw : 0.2f * uw) * aw.w;

            t0 += __shfl_xor_sync(0xffffffffu, t0, 8);
            t1 += __shfl_xor_sync(0xffffffffu, t1, 8);
            t0 += __shfl_xor_sync(0xffffffffu, t0, 4);
            t1 += __shfl_xor_sync(0xffffffffu, t1, 4);
            t0 += __shfl_xor_sync(0xffffffffu, t0, 2);
            t1 += __shfl_xor_sync(0xffffffffu, t1, 2);
            t0 += __shfl_xor_sync(0xffffffffu, t0, 1);
            t1 += __shfl_xor_sync(0xffffffffu, t1, 1);   // per-16-lane (head) sums

            // joint online-softmax update for both edges (exact)
            float mn = fmaxf(mh, fmaxf(t0, t1));
            float sc = __expf(mh - mn);     // 0 when mh == -inf
            float p0 = __expf(t0 - mn);
            float p1 = __expf(t1 - mn);
            den = den * sc + p0 + p1;
            acc.x = acc.x * sc + p0 * g0.x + p1 * g1.x;
            acc.y = acc.y * sc + p0 * g0.y + p1 * g1.y;
            acc.z = acc.z * sc + p0 * g0.z + p1 * g1.z;
            acc.w = acc.w * sc + p0 * g0.w + p1 * g1.w;
            mh = mn;
        }
        // ---- remainder edge ----
        for (; i < end; i++) {
            int s = sp[i];
            float4 g = GL[(size_t)s * 32 + lane];
            float sx = g.x + gr.x, sy = g.y + gr.y, sz = g.z + gr.z, sw = g.w + gr.w;
            float v = (sx > 0.f ? sx : 0.2f * sx) * aw.x
                    + (sy > 0.f ? sy : 0.2f * sy) * aw.y
                    + (sz > 0.f ? sz : 0.2f * sz) * aw.z
                    + (sw > 0.f ? sw : 0.2f * sw) * aw.w;
            v += __shfl_xor_sync(0xffffffffu, v, 8);
            v += __shfl_xor_sync(0xffffffffu, v, 4);
            v += __shfl_xor_sync(0xffffffffu, v, 2);
            v += __shfl_xor_sync(0xffffffffu, v, 1);

            float mn = fmaxf(mh, v);
            float sc = __expf(mh - mn);
            float p  = __expf(v - mn);
            den = den * sc + p;
            acc.x = acc.x * sc + p * g.x;
            acc.y = acc.y * sc + p * g.y;
            acc.z = acc.z * sc + p * g.z;
            acc.w = acc.w * sc + p * g.w;
            mh = mn;
        }
        float inv = 1.f / (den + 1e-16f);
        accT.x += acc.x * inv;
        accT.y += acc.y * inv;
        accT.z += acc.z * inv;
        accT.w += acc.w * inv;
    }
    float4 o;
    o.x = accT.x + bsum.x;
    o.y = accT.y + bsum.y;
    o.z = accT.z + bsum.z;
    o.w = accT.w + bsum.w;
    if (!useDout) {          // inter-layer ReLU folded into the store
        o.x = fmaxf(o.x, 0.f); o.y = fmaxf(o.y, 0.f);
        o.z = fmaxf(o.z, 0.f); o.w = fmaxf(o.w, 0.f);
    }
    ((float4*)OUT)[(size_t)w * 32 + lane] = o;
}

// ---------------- driver ----------------
extern "C" void kernel_launch(void* const* d_in, const int* in_sizes, int n_in,
                              void* d_out, int out_size) {
    const float* xt = (const float*)d_in[0];
    const float* xv = (const float*)d_in[1];
    const float* xe = (const float*)d_in[2];
    const int* e0 = (const int*)d_in[3];
    const int* e1 = (const int*)d_in[4];
    const int* e2 = (const int*)d_in[5];
    const int* e3 = (const int*)d_in[6];
    const int* e4 = (const int*)d_in[7];
    const int* e5 = (const int*)d_in[8];
    const int* e6 = (const int*)d_in[9];
    const int* e7 = (const int*)d_in[10];
    const int* e8 = (const int*)d_in[11];
    const float* Wt = (const float*)d_in[12];
    const float* bt = (const float*)d_in[13];
    const float* Wv = (const float*)d_in[14];
    const float* bv = (const float*)d_in[15];
    const float* We = (const float*)d_in[16];
    const float* be = (const float*)d_in[17];
    const float* Wl1 = (const float*)d_in[18];
    const float* Wr1 = (const float*)d_in[19];
    const float* att1 = (const float*)d_in[20];
    const float* bc1 = (const float*)d_in[21];
    const float* Wl2 = (const float*)d_in[22];
    const float* Wr2 = (const float*)d_in[23];
    const float* att2 = (const float*)d_in[24];
    const float* bc2 = (const float*)d_in[25];

    int M = in_sizes[0] / 16;   // nodes per type
    int E = in_sizes[3] / 2;    // edges per relation
    float* out = (float*)d_out;
    if (M <= 0 || M > NMAX || E <= 0 || E > EMAX) {
        // visible failure mode (rel_err report) instead of empty capture
        zero_out_k<<<(out_size + 255) / 256, 256>>>(out, out_size);
        return;
    }

    // CSR build (per relation, reused by both layers)
    csr_zero<<<(9 * M + 255) / 256, 256>>>(M);
    csr_hist<<<dim3((E + 255) / 256, 9), 256>>>(e0,e1,e2,e3,e4,e5,e6,e7,e8, M, E);
    csr_scan<<<9, 1024>>>(M);
    csr_scatter<<<dim3((E + 255) / 256, 9), 256>>>(e0,e1,e2,e3,e4,e5,e6,e7,e8, M, E);

    // in-projection
    in_proj_k<<<dim3((M * 32 + 255) / 256, 1, 3), 256>>>(xt, xv, xe,
                                                         Wt, bt, Wv, bv, We, be, M);

    dim3 gg((M + 127) / 128, 2, 9);            // y: Wl/Wr side, z: relation
    dim3 fg((M * 32 + 255) / 256, 3);          // y: dst group

    // ---- layer 1 (reads g_H, writes relu(out) back into g_H) ----
    gemm_k<<<gg, 256>>>(Wl1, Wr1, M);
    gat_fused<<<fg, 256>>>(att1, bc1, 0, out, M, E);

    // ---- layer 2 (reads g_H, writes d_out) ----
    gemm_k<<<gg, 256>>>(Wl2, Wr2, M);
    gat_fused<<<fg, 256>>>(att2, bc2, 1, out, M, E);
}